// round 4
// baseline (speedup 1.0000x reference)
#include <cuda_runtime.h>
#include <math.h>
#include <stdint.h>

#define BB 32
#define TT 512
#define HH 512
#define G3 1536

// ---------------------------------------------------------------------------
// Static device scratch (allocation-free)
// ---------------------------------------------------------------------------
__device__ float g_xi[(size_t)BB * TT * G3];    // per-layer input projections
__device__ float g_bufA[(size_t)BB * TT * HH];
__device__ float g_bufB[(size_t)BB * TT * HH];
__device__ float g_h[2][BB * HH];               // double-buffered hidden state
__device__ int   g_flags[128];                  // per-CTA step counters

// ---------------------------------------------------------------------------
// Packed fp32x2 helpers (Blackwell f32x2 pipe: 2x fp32 FMA throughput)
// ---------------------------------------------------------------------------
__device__ __forceinline__ unsigned long long pack2(float lo, float hi) {
    unsigned long long r;
    asm("mov.b64 %0, {%1, %2};" : "=l"(r) : "f"(lo), "f"(hi));
    return r;
}
__device__ __forceinline__ void unpack2(unsigned long long v, float& lo, float& hi) {
    asm("mov.b64 {%0, %1}, %2;" : "=f"(lo), "=f"(hi) : "l"(v));
}
__device__ __forceinline__ void fma2(unsigned long long& d,
                                     unsigned long long a, unsigned long long b) {
    asm("fma.rn.f32x2 %0, %1, %2, %0;" : "+l"(d) : "l"(a), "l"(b));
}
__device__ __forceinline__ int ld_acq(const int* p) {
    int v;
    asm volatile("ld.acquire.gpu.global.b32 %0, [%1];" : "=r"(v) : "l"(p) : "memory");
    return v;
}
__device__ __forceinline__ void st_rel(int* p, int v) {
    asm volatile("st.release.gpu.global.b32 [%0], %1;" :: "l"(p), "r"(v) : "memory");
}

// ---------------------------------------------------------------------------
// Kernel 1: Y[16384,1536] = X[16384,512] @ W[1536,512]^T + bias
// 128x128x16 tiles, 256 threads, 8x8 micro-tile, FFMA2 packed over N-pairs.
// ---------------------------------------------------------------------------
__global__ __launch_bounds__(256) void gemm_kernel(
    const float* __restrict__ X, const float* __restrict__ W,
    const float* __restrict__ bias, float* __restrict__ Y)
{
    __shared__ __align__(16) float Xs[16][132];
    __shared__ __align__(16) float Ws[16][132];

    const int tid = threadIdx.x;
    const int bm = blockIdx.y << 7;
    const int bn = blockIdx.x << 7;
    const int tx = tid & 15;          // 16 N-thread cols
    const int ty = tid >> 4;          // 16 M-thread rows
    const int lr = tid >> 2;          // 0..63 load row
    const int lk = (tid & 3) << 2;    // 0,4,8,12 load k

    const float* Xp = X + (size_t)(bm + lr) * 512 + lk;
    const float* Wp = W + (size_t)(bn + lr) * 512 + lk;

    unsigned long long acc[8][4];
    #pragma unroll
    for (int i = 0; i < 8; i++)
        #pragma unroll
        for (int j = 0; j < 4; j++) acc[i][j] = 0ULL;

    for (int k0 = 0; k0 < 512; k0 += 16) {
        float4 x0 = *(const float4*)(Xp + k0);
        float4 x1 = *(const float4*)(Xp + (size_t)64 * 512 + k0);
        float4 w0 = *(const float4*)(Wp + k0);
        float4 w1 = *(const float4*)(Wp + (size_t)64 * 512 + k0);
        __syncthreads();
        Xs[lk+0][lr] = x0.x; Xs[lk+1][lr] = x0.y; Xs[lk+2][lr] = x0.z; Xs[lk+3][lr] = x0.w;
        Xs[lk+0][lr+64] = x1.x; Xs[lk+1][lr+64] = x1.y; Xs[lk+2][lr+64] = x1.z; Xs[lk+3][lr+64] = x1.w;
        Ws[lk+0][lr] = w0.x; Ws[lk+1][lr] = w0.y; Ws[lk+2][lr] = w0.z; Ws[lk+3][lr] = w0.w;
        Ws[lk+0][lr+64] = w1.x; Ws[lk+1][lr+64] = w1.y; Ws[lk+2][lr+64] = w1.z; Ws[lk+3][lr+64] = w1.w;
        __syncthreads();
        #pragma unroll
        for (int k = 0; k < 16; k++) {
            float4 a0 = *(const float4*)&Xs[k][ty << 3];
            float4 a1 = *(const float4*)&Xs[k][(ty << 3) + 4];
            ulonglong2 b01 = *(const ulonglong2*)&Ws[k][tx << 3];
            ulonglong2 b23 = *(const ulonglong2*)&Ws[k][(tx << 3) + 4];
            unsigned long long av[8];
            av[0] = pack2(a0.x, a0.x); av[1] = pack2(a0.y, a0.y);
            av[2] = pack2(a0.z, a0.z); av[3] = pack2(a0.w, a0.w);
            av[4] = pack2(a1.x, a1.x); av[5] = pack2(a1.y, a1.y);
            av[6] = pack2(a1.z, a1.z); av[7] = pack2(a1.w, a1.w);
            #pragma unroll
            for (int i = 0; i < 8; i++) {
                fma2(acc[i][0], av[i], b01.x);
                fma2(acc[i][1], av[i], b01.y);
                fma2(acc[i][2], av[i], b23.x);
                fma2(acc[i][3], av[i], b23.y);
            }
        }
    }

    #pragma unroll
    for (int i = 0; i < 8; i++) {
        const int m = bm + (ty << 3) + i;
        const int n = bn + (tx << 3);
        float r[8];
        unpack2(acc[i][0], r[0], r[1]);
        unpack2(acc[i][1], r[2], r[3]);
        unpack2(acc[i][2], r[4], r[5]);
        unpack2(acc[i][3], r[6], r[7]);
        float4 o0, o1;
        o0.x = r[0] + bias[n+0]; o0.y = r[1] + bias[n+1];
        o0.z = r[2] + bias[n+2]; o0.w = r[3] + bias[n+3];
        o1.x = r[4] + bias[n+4]; o1.y = r[5] + bias[n+5];
        o1.z = r[6] + bias[n+6]; o1.w = r[7] + bias[n+7];
        *(float4*)(Y + (size_t)m * G3 + n)     = o0;
        *(float4*)(Y + (size_t)m * G3 + n + 4) = o1;
    }
}

// ---------------------------------------------------------------------------
// Kernel 2: reset flags
// ---------------------------------------------------------------------------
__global__ void reset_kernel() {
    int i = threadIdx.x;
    if (i < 128) g_flags[i] = 0;
}

// ---------------------------------------------------------------------------
// Kernel 3: persistent GRU scan, one layer.
// 128 CTAs = 8 batch-groups (4 batches) x 16 j-slices (32 j's).
// Whh slice (96 rows x 512, split-padded) in SMEM; per-step group sync
// via release/acquire flags through L2 (all CTAs co-resident).
// ---------------------------------------------------------------------------
#define WST 544   // 8 blocks of 68 floats (64 data + 4 pad) -> phase-conflict-free
#define SCAN_SMEM_FLOATS (96 * WST + 4 * WST + 96 * 4 + 96)
#define SCAN_SMEM_BYTES  (SCAN_SMEM_FLOATS * 4)

__global__ __launch_bounds__(192, 1) void scan_kernel(
    const float* __restrict__ xi, const float* __restrict__ Whh,
    const float* __restrict__ bhh, float* __restrict__ out, int base)
{
    extern __shared__ __align__(16) float sm[];
    float* Wsm = sm;                  // [96][544]  padded Whh slice
    float* Hs  = sm + 96 * WST;       // [4][544]   padded h_{t-1} (own batches)
    float* HHs = Hs + 4 * WST;        // [96][4]    reduced hh
    float* Bs  = HHs + 96 * 4;        // [96]       bhh slice

    const int tid = threadIdx.x;
    const int cta = blockIdx.x;
    const int g = cta >> 4;           // batch group 0..7
    const int slice = cta & 15;
    const int j0 = slice * 32;

    // ---- load Whh slice (rows m = gate*32 + jj), padded layout ----
    for (int i = tid; i < 96 * 128; i += 192) {
        int m = i >> 7;
        int k = (i & 127) << 2;
        int gate = m >> 5, jj = m & 31;
        float4 v = *(const float4*)(Whh + ((size_t)(gate * 512 + j0 + jj)) * 512 + k);
        *(float4*)(Wsm + m * WST + (k >> 6) * 68 + (k & 63)) = v;
    }
    if (tid < 96) {
        int gate = tid >> 5, jj = tid & 31;
        Bs[tid] = bhh[gate * 512 + j0 + jj];
        HHs[tid * 4 + 0] = 0.f; HHs[tid * 4 + 1] = 0.f;
        HHs[tid * 4 + 2] = 0.f; HHs[tid * 4 + 3] = 0.f;
    }
    __syncthreads();

    const int rg = tid >> 4;                      // 0..11 (8 rows each)
    const int split = tid & 15;                   // 0..15 (32-k segments)
    const int sbase = (split & 7) * 68 + (split >> 3) * 32;

    const int gb = tid >> 5;                      // gate-phase batch (0..3 used)
    const int gj = tid & 31;
    const int bglob = g * 4 + gb;
    const int jglob = j0 + gj;
    const int hp_idx = (gb < 4) ? (gb * WST + (jglob >> 6) * 68 + (jglob & 63)) : 0;

    int* myflags = g_flags + g * 16;

    for (int t = 0; t < TT; t++) {
        // prefetch xi for this step (independent of h; hides DRAM latency)
        float xr = 0.f, xz = 0.f, xn = 0.f;
        if (tid < 128) {
            const float* p = xi + ((size_t)bglob * TT + t) * G3 + jglob;
            xr = __ldg(p); xz = __ldg(p + 512); xn = __ldg(p + 1024);
        }

        if (t > 0) {
            // wait for group to publish h_{t-1}
            if (tid < 16) {
                int tgt = base + t;
                while (ld_acq(&myflags[tid]) < tgt) { }
            }
            __syncthreads();

            // load h_{t-1} for own 4 batches into padded SMEM
            const float* hsrc = g_h[t & 1] + (size_t)g * 4 * 512;
            for (int i = tid; i < 512; i += 192) {
                int b = i >> 7;
                int k = (i & 127) << 2;
                float4 v = *(const float4*)(hsrc + b * 512 + k);
                *(float4*)(Hs + b * WST + (k >> 6) * 68 + (k & 63)) = v;
            }
            __syncthreads();

            // hh = h @ Whh_slice^T : per-thread 8 rows x 4 batches x 32 k (f32x2)
            unsigned long long acc[8][4];
            #pragma unroll
            for (int r = 0; r < 8; r++)
                #pragma unroll
                for (int b = 0; b < 4; b++) acc[r][b] = 0ULL;

            const float* wbase = Wsm + (rg * 8) * WST + sbase;
            const float* hbase = Hs + sbase;
            #pragma unroll
            for (int q = 0; q < 8; q++) {
                ulonglong2 hv[4];
                #pragma unroll
                for (int b = 0; b < 4; b++)
                    hv[b] = *(const ulonglong2*)(hbase + b * WST + q * 4);
                #pragma unroll
                for (int r = 0; r < 8; r++) {
                    ulonglong2 wv = *(const ulonglong2*)(wbase + r * WST + q * 4);
                    #pragma unroll
                    for (int b = 0; b < 4; b++) {
                        fma2(acc[r][b], wv.x, hv[b].x);
                        fma2(acc[r][b], wv.y, hv[b].y);
                    }
                }
            }

            // reduce over 16 k-splits (lane bits 0..3), write to HHs
            #pragma unroll
            for (int r = 0; r < 8; r++) {
                #pragma unroll
                for (int b = 0; b < 4; b++) {
                    float lo, hi;
                    unpack2(acc[r][b], lo, hi);
                    float v = lo + hi;
                    v += __shfl_xor_sync(0xffffffffu, v, 1);
                    v += __shfl_xor_sync(0xffffffffu, v, 2);
                    v += __shfl_xor_sync(0xffffffffu, v, 4);
                    v += __shfl_xor_sync(0xffffffffu, v, 8);
                    if (split == 0) HHs[(rg * 8 + r) * 4 + b] = v;
                }
            }
            __syncthreads();
        }

        // gate math + publish (128 threads: 4 batches x 32 j)
        if (tid < 128) {
            float hr = HHs[(     gj) * 4 + gb] + Bs[     gj];
            float hz = HHs[(32 + gj) * 4 + gb] + Bs[32 + gj];
            float hn = HHs[(64 + gj) * 4 + gb] + Bs[64 + gj];
            float hp = (t > 0) ? Hs[hp_idx] : 0.f;
            float rr = 1.f / (1.f + __expf(-(xr + hr)));
            float zz = 1.f / (1.f + __expf(-(xz + hz)));
            float nn = tanhf(xn + rr * hn);
            float hnew = (1.f - zz) * nn + zz * hp;
            g_h[(t + 1) & 1][(size_t)bglob * 512 + jglob] = hnew;
            out[((size_t)bglob * TT + t) * HH + jglob] = hnew;
        }
        __syncthreads();
        if (tid == 0) st_rel(&g_flags[cta], base + t + 1);
    }
}

// ---------------------------------------------------------------------------
// Kernel 4: mask (t >= len -> 0) + LayerNorm per [b,t] row
// ---------------------------------------------------------------------------
__global__ __launch_bounds__(128) void ln_kernel(
    const float* __restrict__ in, float* __restrict__ out,
    const float* __restrict__ gamma, const float* __restrict__ beta,
    const int* __restrict__ lens)
{
    const int t = blockIdx.x, b = blockIdx.y;
    const int tid = threadIdx.x;
    const bool valid = t < lens[b];
    const float4* row = (const float4*)(in + ((size_t)b * TT + t) * HH);
    float4 v = valid ? row[tid] : make_float4(0.f, 0.f, 0.f, 0.f);
    float s = v.x + v.y + v.z + v.w;
    float q = v.x * v.x + v.y * v.y + v.z * v.z + v.w * v.w;
    #pragma unroll
    for (int o = 16; o; o >>= 1) {
        s += __shfl_xor_sync(0xffffffffu, s, o);
        q += __shfl_xor_sync(0xffffffffu, q, o);
    }
    __shared__ float ss[4], qq[4];
    if ((tid & 31) == 0) { ss[tid >> 5] = s; qq[tid >> 5] = q; }
    __syncthreads();
    s = ss[0] + ss[1] + ss[2] + ss[3];
    q = qq[0] + qq[1] + qq[2] + qq[3];
    const float mu = s * (1.f / 512.f);
    const float var = q * (1.f / 512.f) - mu * mu;
    const float rstd = rsqrtf(var + 1e-5f);
    const float4 gm = ((const float4*)gamma)[tid];
    const float4 bt = ((const float4*)beta)[tid];
    float4 o;
    o.x = (v.x - mu) * rstd * gm.x + bt.x;
    o.y = (v.y - mu) * rstd * gm.y + bt.y;
    o.z = (v.z - mu) * rstd * gm.z + bt.z;
    o.w = (v.w - mu) * rstd * gm.w + bt.w;
    ((float4*)(out + ((size_t)b * TT + t) * HH))[tid] = o;
}

// ---------------------------------------------------------------------------
// Launch
// ---------------------------------------------------------------------------
extern "C" void kernel_launch(void* const* d_in, const int* in_sizes, int n_in,
                              void* d_out, int out_size)
{
    (void)in_sizes; (void)n_in; (void)out_size;
    const float* x     = (const float*)d_in[0];
    const float* Wih   = (const float*)d_in[1];
    const float* Whh   = (const float*)d_in[2];
    const float* bih   = (const float*)d_in[3];
    const float* bhh   = (const float*)d_in[4];
    const float* gamma = (const float*)d_in[5];
    const float* beta  = (const float*)d_in[6];
    const int*   lens  = (const int*)d_in[7];
    float* out = (float*)d_out;

    float *xi, *bufA, *bufB;
    cudaGetSymbolAddress((void**)&xi,   g_xi);
    cudaGetSymbolAddress((void**)&bufA, g_bufA);
    cudaGetSymbolAddress((void**)&bufB, g_bufB);

    cudaFuncSetAttribute(scan_kernel,
                         cudaFuncAttributeMaxDynamicSharedMemorySize,
                         SCAN_SMEM_BYTES);

    reset_kernel<<<1, 128>>>();

    const dim3 gg(12, 128);
    const size_t WL = (size_t)G3 * HH;

    // GRU 0
    gemm_kernel<<<gg, 256>>>(x, Wih, bih, xi);
    scan_kernel<<<128, 192, SCAN_SMEM_BYTES>>>(xi, Whh, bhh, bufA, 0);
    // GRU 1
    gemm_kernel<<<gg, 256>>>(bufA, Wih + WL, bih + G3, xi);
    scan_kernel<<<128, 192, SCAN_SMEM_BYTES>>>(xi, Whh + WL, bhh + G3, bufB, 512);
    // mask + LN 0
    ln_kernel<<<dim3(TT, BB), 128>>>(bufB, bufA, gamma, beta, lens);
    // GRU 2
    gemm_kernel<<<gg, 256>>>(bufA, Wih + 2 * WL, bih + 2 * G3, xi);
    scan_kernel<<<128, 192, SCAN_SMEM_BYTES>>>(xi, Whh + 2 * WL, bhh + 2 * G3, bufB, 1024);
    // GRU 3
    gemm_kernel<<<gg, 256>>>(bufB, Wih + 3 * WL, bih + 3 * G3, xi);
    scan_kernel<<<128, 192, SCAN_SMEM_BYTES>>>(xi, Whh + 3 * WL, bhh + 3 * G3, bufA, 1536);
    // mask + LN 1 -> output
    ln_kernel<<<dim3(TT, BB), 128>>>(bufA, out, gamma + HH, beta + HH, lens);
}

// round 5
// speedup vs baseline: 1.0237x; 1.0237x over previous
#include <cuda_runtime.h>
#include <math.h>
#include <stdint.h>

#define BB 32
#define TT 512
#define HH 512
#define G3 1536

// ---------------------------------------------------------------------------
// Static device scratch (allocation-free)
// ---------------------------------------------------------------------------
__device__ float g_xi[(size_t)BB * TT * G3];    // per-layer input projections
__device__ float g_bufA[(size_t)BB * TT * HH];
__device__ float g_bufB[(size_t)BB * TT * HH];
__device__ float g_h[2][BB * HH];               // double-buffered hidden state
__device__ int   g_flags[128];                  // per-CTA step counters

// ---------------------------------------------------------------------------
// Packed fp32x2 helpers (Blackwell f32x2 pipe: 2x fp32 FMA throughput)
// ---------------------------------------------------------------------------
__device__ __forceinline__ unsigned long long pack2(float lo, float hi) {
    unsigned long long r;
    asm("mov.b64 %0, {%1, %2};" : "=l"(r) : "f"(lo), "f"(hi));
    return r;
}
__device__ __forceinline__ void unpack2(unsigned long long v, float& lo, float& hi) {
    asm("mov.b64 {%0, %1}, %2;" : "=f"(lo), "=f"(hi) : "l"(v));
}
__device__ __forceinline__ void fma2(unsigned long long& d,
                                     unsigned long long a, unsigned long long b) {
    asm("fma.rn.f32x2 %0, %1, %2, %0;" : "+l"(d) : "l"(a), "l"(b));
}
__device__ __forceinline__ int ld_acq(const int* p) {
    int v;
    asm volatile("ld.acquire.gpu.global.b32 %0, [%1];" : "=r"(v) : "l"(p) : "memory");
    return v;
}
__device__ __forceinline__ void st_rel(int* p, int v) {
    asm volatile("st.release.gpu.global.b32 [%0], %1;" :: "l"(p), "r"(v) : "memory");
}

// ---------------------------------------------------------------------------
// Kernel 1: Y[16384,1536] = X[16384,512] @ W[1536,512]^T + bias
// 128x128x16 tiles, 256 threads, 8x8 micro-tile, FFMA2 packed over N-pairs.
// ---------------------------------------------------------------------------
__global__ __launch_bounds__(256) void gemm_kernel(
    const float* __restrict__ X, const float* __restrict__ W,
    const float* __restrict__ bias, float* __restrict__ Y)
{
    __shared__ __align__(16) float Xs[16][132];
    __shared__ __align__(16) float Ws[16][132];

    const int tid = threadIdx.x;
    const int bm = blockIdx.y << 7;
    const int bn = blockIdx.x << 7;
    const int tx = tid & 15;          // 16 N-thread cols
    const int ty = tid >> 4;          // 16 M-thread rows
    const int lr = tid >> 2;          // 0..63 load row
    const int lk = (tid & 3) << 2;    // 0,4,8,12 load k

    const float* Xp = X + (size_t)(bm + lr) * 512 + lk;
    const float* Wp = W + (size_t)(bn + lr) * 512 + lk;

    unsigned long long acc[8][4];
    #pragma unroll
    for (int i = 0; i < 8; i++)
        #pragma unroll
        for (int j = 0; j < 4; j++) acc[i][j] = 0ULL;

    for (int k0 = 0; k0 < 512; k0 += 16) {
        float4 x0 = *(const float4*)(Xp + k0);
        float4 x1 = *(const float4*)(Xp + (size_t)64 * 512 + k0);
        float4 w0 = *(const float4*)(Wp + k0);
        float4 w1 = *(const float4*)(Wp + (size_t)64 * 512 + k0);
        __syncthreads();
        Xs[lk+0][lr] = x0.x; Xs[lk+1][lr] = x0.y; Xs[lk+2][lr] = x0.z; Xs[lk+3][lr] = x0.w;
        Xs[lk+0][lr+64] = x1.x; Xs[lk+1][lr+64] = x1.y; Xs[lk+2][lr+64] = x1.z; Xs[lk+3][lr+64] = x1.w;
        Ws[lk+0][lr] = w0.x; Ws[lk+1][lr] = w0.y; Ws[lk+2][lr] = w0.z; Ws[lk+3][lr] = w0.w;
        Ws[lk+0][lr+64] = w1.x; Ws[lk+1][lr+64] = w1.y; Ws[lk+2][lr+64] = w1.z; Ws[lk+3][lr+64] = w1.w;
        __syncthreads();
        #pragma unroll
        for (int k = 0; k < 16; k++) {
            float4 a0 = *(const float4*)&Xs[k][ty << 3];
            float4 a1 = *(const float4*)&Xs[k][(ty << 3) + 4];
            ulonglong2 b01 = *(const ulonglong2*)&Ws[k][tx << 3];
            ulonglong2 b23 = *(const ulonglong2*)&Ws[k][(tx << 3) + 4];
            unsigned long long av[8];
            av[0] = pack2(a0.x, a0.x); av[1] = pack2(a0.y, a0.y);
            av[2] = pack2(a0.z, a0.z); av[3] = pack2(a0.w, a0.w);
            av[4] = pack2(a1.x, a1.x); av[5] = pack2(a1.y, a1.y);
            av[6] = pack2(a1.z, a1.z); av[7] = pack2(a1.w, a1.w);
            #pragma unroll
            for (int i = 0; i < 8; i++) {
                fma2(acc[i][0], av[i], b01.x);
                fma2(acc[i][1], av[i], b01.y);
                fma2(acc[i][2], av[i], b23.x);
                fma2(acc[i][3], av[i], b23.y);
            }
        }
    }

    #pragma unroll
    for (int i = 0; i < 8; i++) {
        const int m = bm + (ty << 3) + i;
        const int n = bn + (tx << 3);
        float r[8];
        unpack2(acc[i][0], r[0], r[1]);
        unpack2(acc[i][1], r[2], r[3]);
        unpack2(acc[i][2], r[4], r[5]);
        unpack2(acc[i][3], r[6], r[7]);
        float4 o0, o1;
        o0.x = r[0] + bias[n+0]; o0.y = r[1] + bias[n+1];
        o0.z = r[2] + bias[n+2]; o0.w = r[3] + bias[n+3];
        o1.x = r[4] + bias[n+4]; o1.y = r[5] + bias[n+5];
        o1.z = r[6] + bias[n+6]; o1.w = r[7] + bias[n+7];
        *(float4*)(Y + (size_t)m * G3 + n)     = o0;
        *(float4*)(Y + (size_t)m * G3 + n + 4) = o1;
    }
}

// ---------------------------------------------------------------------------
// Kernel 2: reset flags
// ---------------------------------------------------------------------------
__global__ void reset_kernel() {
    int i = threadIdx.x;
    if (i < 128) g_flags[i] = 0;
}

// ---------------------------------------------------------------------------
// Kernel 3: persistent GRU scan, one layer.
// 128 CTAs = 8 batch-groups (4 batches) x 16 j-slices (32 j's).
// Whh slice (96 rows x 512, split-padded) in SMEM; per-step group sync
// via release/acquire flags through L2 (all CTAs co-resident).
// ---------------------------------------------------------------------------
#define WST 544   // 8 blocks of 68 floats (64 data + 4 pad) -> phase-conflict-free
#define SCAN_SMEM_FLOATS (96 * WST + 4 * WST + 96 * 4 + 96)
#define SCAN_SMEM_BYTES  (SCAN_SMEM_FLOATS * 4)

__global__ __launch_bounds__(192, 1) void scan_kernel(
    const float* __restrict__ xi, const float* __restrict__ Whh,
    const float* __restrict__ bhh, float* __restrict__ out, int base)
{
    extern __shared__ __align__(16) float sm[];
    float* Wsm = sm;                  // [96][544]  padded Whh slice
    float* Hs  = sm + 96 * WST;       // [4][544]   padded h_{t-1} (own batches)
    float* HHs = Hs + 4 * WST;        // [96][4]    reduced hh
    float* Bs  = HHs + 96 * 4;        // [96]       bhh slice

    const int tid = threadIdx.x;
    const int cta = blockIdx.x;
    const int g = cta >> 4;           // batch group 0..7
    const int slice = cta & 15;
    const int j0 = slice * 32;

    // ---- load Whh slice (rows m = gate*32 + jj), padded layout ----
    for (int i = tid; i < 96 * 128; i += 192) {
        int m = i >> 7;
        int k = (i & 127) << 2;
        int gate = m >> 5, jj = m & 31;
        float4 v = *(const float4*)(Whh + ((size_t)(gate * 512 + j0 + jj)) * 512 + k);
        *(float4*)(Wsm + m * WST + (k >> 6) * 68 + (k & 63)) = v;
    }
    if (tid < 96) {
        int gate = tid >> 5, jj = tid & 31;
        Bs[tid] = bhh[gate * 512 + j0 + jj];
        HHs[tid * 4 + 0] = 0.f; HHs[tid * 4 + 1] = 0.f;
        HHs[tid * 4 + 2] = 0.f; HHs[tid * 4 + 3] = 0.f;
    }
    __syncthreads();

    const int rg = tid >> 4;                      // 0..11 (8 rows each)
    const int split = tid & 15;                   // 0..15 (32-k segments)
    const int sbase = (split & 7) * 68 + (split >> 3) * 32;

    const int gb = tid >> 5;                      // gate-phase batch (0..3 used)
    const int gj = tid & 31;
    const int bglob = g * 4 + gb;
    const int jglob = j0 + gj;
    const int hp_idx = (gb < 4) ? (gb * WST + (jglob >> 6) * 68 + (jglob & 63)) : 0;

    int* myflags = g_flags + g * 16;

    for (int t = 0; t < TT; t++) {
        // prefetch xi for this step (independent of h; hides DRAM latency)
        float xr = 0.f, xz = 0.f, xn = 0.f;
        if (tid < 128) {
            const float* p = xi + ((size_t)bglob * TT + t) * G3 + jglob;
            xr = __ldg(p); xz = __ldg(p + 512); xn = __ldg(p + 1024);
        }

        if (t > 0) {
            // wait for group to publish h_{t-1}
            if (tid < 16) {
                int tgt = base + t;
                while (ld_acq(&myflags[tid]) < tgt) { }
            }
            __syncthreads();

            // load h_{t-1} for own 4 batches into padded SMEM
            const float* hsrc = g_h[t & 1] + (size_t)g * 4 * 512;
            for (int i = tid; i < 512; i += 192) {
                int b = i >> 7;
                int k = (i & 127) << 2;
                float4 v = *(const float4*)(hsrc + b * 512 + k);
                *(float4*)(Hs + b * WST + (k >> 6) * 68 + (k & 63)) = v;
            }
            __syncthreads();

            // hh = h @ Whh_slice^T : per-thread 8 rows x 4 batches x 32 k (f32x2)
            unsigned long long acc[8][4];
            #pragma unroll
            for (int r = 0; r < 8; r++)
                #pragma unroll
                for (int b = 0; b < 4; b++) acc[r][b] = 0ULL;

            const float* wbase = Wsm + (rg * 8) * WST + sbase;
            const float* hbase = Hs + sbase;
            #pragma unroll
            for (int q = 0; q < 8; q++) {
                ulonglong2 hv[4];
                #pragma unroll
                for (int b = 0; b < 4; b++)
                    hv[b] = *(const ulonglong2*)(hbase + b * WST + q * 4);
                #pragma unroll
                for (int r = 0; r < 8; r++) {
                    ulonglong2 wv = *(const ulonglong2*)(wbase + r * WST + q * 4);
                    #pragma unroll
                    for (int b = 0; b < 4; b++) {
                        fma2(acc[r][b], wv.x, hv[b].x);
                        fma2(acc[r][b], wv.y, hv[b].y);
                    }
                }
            }

            // reduce over 16 k-splits (lane bits 0..3), write to HHs
            #pragma unroll
            for (int r = 0; r < 8; r++) {
                #pragma unroll
                for (int b = 0; b < 4; b++) {
                    float lo, hi;
                    unpack2(acc[r][b], lo, hi);
                    float v = lo + hi;
                    v += __shfl_xor_sync(0xffffffffu, v, 1);
                    v += __shfl_xor_sync(0xffffffffu, v, 2);
                    v += __shfl_xor_sync(0xffffffffu, v, 4);
                    v += __shfl_xor_sync(0xffffffffu, v, 8);
                    if (split == 0) HHs[(rg * 8 + r) * 4 + b] = v;
                }
            }
            __syncthreads();
        }

        // gate math + publish (128 threads: 4 batches x 32 j)
        if (tid < 128) {
            float hr = HHs[(     gj) * 4 + gb] + Bs[     gj];
            float hz = HHs[(32 + gj) * 4 + gb] + Bs[32 + gj];
            float hn = HHs[(64 + gj) * 4 + gb] + Bs[64 + gj];
            float hp = (t > 0) ? Hs[hp_idx] : 0.f;
            float rr = 1.f / (1.f + __expf(-(xr + hr)));
            float zz = 1.f / (1.f + __expf(-(xz + hz)));
            float nn = tanhf(xn + rr * hn);
            float hnew = (1.f - zz) * nn + zz * hp;
            g_h[(t + 1) & 1][(size_t)bglob * 512 + jglob] = hnew;
            out[((size_t)bglob * TT + t) * HH + jglob] = hnew;
        }
        __syncthreads();
        if (tid == 0) st_rel(&g_flags[cta], base + t + 1);
    }
}

// ---------------------------------------------------------------------------
// Kernel 4: mask (t >= len -> 0) + LayerNorm per [b,t] row
// ---------------------------------------------------------------------------
__global__ __launch_bounds__(128) void ln_kernel(
    const float* __restrict__ in, float* __restrict__ out,
    const float* __restrict__ gamma, const float* __restrict__ beta,
    const int* __restrict__ lens)
{
    const int t = blockIdx.x, b = blockIdx.y;
    const int tid = threadIdx.x;
    const bool valid = t < lens[b];
    const float4* row = (const float4*)(in + ((size_t)b * TT + t) * HH);
    float4 v = valid ? row[tid] : make_float4(0.f, 0.f, 0.f, 0.f);
    float s = v.x + v.y + v.z + v.w;
    float q = v.x * v.x + v.y * v.y + v.z * v.z + v.w * v.w;
    #pragma unroll
    for (int o = 16; o; o >>= 1) {
        s += __shfl_xor_sync(0xffffffffu, s, o);
        q += __shfl_xor_sync(0xffffffffu, q, o);
    }
    __shared__ float ss[4], qq[4];
    if ((tid & 31) == 0) { ss[tid >> 5] = s; qq[tid >> 5] = q; }
    __syncthreads();
    s = ss[0] + ss[1] + ss[2] + ss[3];
    q = qq[0] + qq[1] + qq[2] + qq[3];
    const float mu = s * (1.f / 512.f);
    const float var = q * (1.f / 512.f) - mu * mu;
    const float rstd = rsqrtf(var + 1e-5f);
    const float4 gm = ((const float4*)gamma)[tid];
    const float4 bt = ((const float4*)beta)[tid];
    float4 o;
    o.x = (v.x - mu) * rstd * gm.x + bt.x;
    o.y = (v.y - mu) * rstd * gm.y + bt.y;
    o.z = (v.z - mu) * rstd * gm.z + bt.z;
    o.w = (v.w - mu) * rstd * gm.w + bt.w;
    ((float4*)(out + ((size_t)b * TT + t) * HH))[tid] = o;
}

// ---------------------------------------------------------------------------
// Launch
// ---------------------------------------------------------------------------
extern "C" void kernel_launch(void* const* d_in, const int* in_sizes, int n_in,
                              void* d_out, int out_size)
{
    (void)in_sizes; (void)n_in; (void)out_size;
    const float* x     = (const float*)d_in[0];
    const float* Wih   = (const float*)d_in[1];
    const float* Whh   = (const float*)d_in[2];
    const float* bih   = (const float*)d_in[3];
    const float* bhh   = (const float*)d_in[4];
    const float* gamma = (const float*)d_in[5];
    const float* beta  = (const float*)d_in[6];
    const int*   lens  = (const int*)d_in[7];
    float* out = (float*)d_out;

    float *xi, *bufA, *bufB;
    cudaGetSymbolAddress((void**)&xi,   g_xi);
    cudaGetSymbolAddress((void**)&bufA, g_bufA);
    cudaGetSymbolAddress((void**)&bufB, g_bufB);

    cudaFuncSetAttribute(scan_kernel,
                         cudaFuncAttributeMaxDynamicSharedMemorySize,
                         SCAN_SMEM_BYTES);

    reset_kernel<<<1, 128>>>();

    const dim3 gg(12, 128);
    const size_t WL = (size_t)G3 * HH;

    // GRU 0
    gemm_kernel<<<gg, 256>>>(x, Wih, bih, xi);
    scan_kernel<<<128, 192, SCAN_SMEM_BYTES>>>(xi, Whh, bhh, bufA, 0);
    // GRU 1
    gemm_kernel<<<gg, 256>>>(bufA, Wih + WL, bih + G3, xi);
    scan_kernel<<<128, 192, SCAN_SMEM_BYTES>>>(xi, Whh + WL, bhh + G3, bufB, 512);
    // mask + LN 0
    ln_kernel<<<dim3(TT, BB), 128>>>(bufB, bufA, gamma, beta, lens);
    // GRU 2
    gemm_kernel<<<gg, 256>>>(bufA, Wih + 2 * WL, bih + 2 * G3, xi);
    scan_kernel<<<128, 192, SCAN_SMEM_BYTES>>>(xi, Whh + 2 * WL, bhh + 2 * G3, bufB, 1024);
    // GRU 3
    gemm_kernel<<<gg, 256>>>(bufB, Wih + 3 * WL, bih + 3 * G3, xi);
    scan_kernel<<<128, 192, SCAN_SMEM_BYTES>>>(xi, Whh + 3 * WL, bhh + 3 * G3, bufA, 1536);
    // mask + LN 1 -> output
    ln_kernel<<<dim3(TT, BB), 128>>>(bufA, out, gamma + HH, beta + HH, lens);
}